// round 10
// baseline (speedup 1.0000x reference)
#include <cuda_runtime.h>

#define DD 4096
#define THREADS 1024          // 32 warps, one block per SM
#define MATSZ ((size_t)DD * DD)

// ping-pong node buffers (scatter idx is a permutation -> fully overwritten each layer)
__device__ float g_buf0[DD];
__device__ float g_buf1[DD];

template<bool MASK, bool GATHER, bool SCATTER>
__global__ void __launch_bounds__(THREADS, 1)
gemv_layer(const float* __restrict__ W,
           const float* __restrict__ O,
           const float* __restrict__ bias,
           const float* __restrict__ src,
           const int*   __restrict__ gidx,
           const int*   __restrict__ sidx,
           float*       __restrict__ dst)
{
    __shared__ float s_in[DD];
    const int t    = threadIdx.x;
    const int lane = t & 31;
    const int w    = t >> 5;

    // static balanced row partition over the ACTUAL SM count (gridDim.x = #SMs)
    const int nsm     = gridDim.x;
    const int r_start = (int)(((long long)blockIdx.x * DD) / nsm);
    const int r_end   = (int)(((long long)(blockIdx.x + 1) * DD) / nsm);
    const int row     = r_start + w;
    const bool has_row = row < r_end;

    const float4* __restrict__ w4 = reinterpret_cast<const float4*>(W + (size_t)row * DD) + lane;
    const float4* __restrict__ o4 = MASK
        ? reinterpret_cast<const float4*>(O + (size_t)row * DD) + lane : nullptr;

    // ---------- pre-sync phase: first W/O batch + epilogue scalars overlap the gather ----------
    float4 wb[MASK ? 4 : 8], ob[MASK ? 4 : 1];
    float bv = 0.f; int sc = 0;
    if (has_row) {
        if (MASK) {
            #pragma unroll
            for (int u = 0; u < 4; ++u) wb[u] = __ldcs(w4 + u * 32);
            #pragma unroll
            for (int u = 0; u < 4; ++u) ob[u] = __ldcs(o4 + u * 32);
        } else {
            #pragma unroll
            for (int u = 0; u < 8; ++u) wb[u] = __ldcs(w4 + u * 32);
        }
        if (lane == 0) {
            bv = __ldg(bias + row);
            sc = SCATTER ? __ldg(sidx + row) : row;
        }
    }

    // ---------- gather input vector into smem (4 independent loads -> one round trip) ----------
    {
        float tmp[4];
        if (GATHER) {
            int gi[4];
            #pragma unroll
            for (int r = 0; r < 4; ++r) gi[r] = __ldg(gidx + t + r * THREADS);
            #pragma unroll
            for (int r = 0; r < 4; ++r) tmp[r] = __ldcg(src + gi[r]);   // L1 bypass: fresh data
        } else {
            #pragma unroll
            for (int r = 0; r < 4; ++r) tmp[r] = __ldg(src + t + r * THREADS);
        }
        #pragma unroll
        for (int r = 0; r < 4; ++r) s_in[t + r * THREADS] = tmp[r];
    }
    __syncthreads();

    if (!has_row) return;

    const float4* __restrict__ s4 = reinterpret_cast<const float4*>(s_in) + lane;
    float acc0 = 0.f, acc1 = 0.f;

    if (MASK) {
        // consume preloaded batch 0
        #pragma unroll
        for (int u = 0; u < 4; ++u) {
            const float4 xi = s4[u * 32];
            acc0 = fmaf(wb[u].x * ob[u].x, xi.x, acc0);
            acc1 = fmaf(wb[u].y * ob[u].y, xi.y, acc1);
            acc0 = fmaf(wb[u].z * ob[u].z, xi.z, acc0);
            acc1 = fmaf(wb[u].w * ob[u].w, xi.w, acc1);
        }
        // batches 1..7: R3's proven load-then-consume form
        #pragma unroll
        for (int base = 4; base < 32; base += 4) {
            #pragma unroll
            for (int u = 0; u < 4; ++u) wb[u] = __ldcs(w4 + (base + u) * 32);
            #pragma unroll
            for (int u = 0; u < 4; ++u) ob[u] = __ldcs(o4 + (base + u) * 32);
            #pragma unroll
            for (int u = 0; u < 4; ++u) {
                const float4 xi = s4[(base + u) * 32];
                acc0 = fmaf(wb[u].x * ob[u].x, xi.x, acc0);
                acc1 = fmaf(wb[u].y * ob[u].y, xi.y, acc1);
                acc0 = fmaf(wb[u].z * ob[u].z, xi.z, acc0);
                acc1 = fmaf(wb[u].w * ob[u].w, xi.w, acc1);
            }
        }
    } else {
        #pragma unroll
        for (int u = 0; u < 8; ++u) {
            const float4 xi = s4[u * 32];
            acc0 = fmaf(wb[u].x, xi.x, acc0);
            acc1 = fmaf(wb[u].y, xi.y, acc1);
            acc0 = fmaf(wb[u].z, xi.z, acc0);
            acc1 = fmaf(wb[u].w, xi.w, acc1);
        }
        #pragma unroll
        for (int base = 8; base < 32; base += 8) {
            #pragma unroll
            for (int u = 0; u < 8; ++u) wb[u] = __ldcs(w4 + (base + u) * 32);
            #pragma unroll
            for (int u = 0; u < 8; ++u) {
                const float4 xi = s4[(base + u) * 32];
                acc0 = fmaf(wb[u].x, xi.x, acc0);
                acc1 = fmaf(wb[u].y, xi.y, acc1);
                acc0 = fmaf(wb[u].z, xi.z, acc0);
                acc1 = fmaf(wb[u].w, xi.w, acc1);
            }
        }
    }

    float acc = acc0 + acc1;
    #pragma unroll
    for (int off = 16; off; off >>= 1) acc += __shfl_down_sync(0xffffffffu, acc, off);

    if (lane == 0) dst[sc] = fmaxf(acc + bv, 0.f);
}

extern "C" void kernel_launch(void* const* d_in, const int* in_sizes, int n_in,
                              void* d_out, int out_size)
{
    const float* x       = (const float*)d_in[0];   // [D]
    const float* W_in    = (const float*)d_in[1];   // [D, D]
    const float* b_in    = (const float*)d_in[2];   // [D]
    const float* weights = (const float*)d_in[3];   // [L, D, D]
    const float* orders  = (const float*)d_in[4];   // [L, D, D]
    const float* biases  = (const float*)d_in[5];   // [L, D]
    const int*   gidx    = (const int*)d_in[6];     // [L, D]
    const int*   sidx    = (const int*)d_in[7];     // [L+1, D]
    float*       out     = (float*)d_out;           // [D]

    float *b0 = nullptr, *b1 = nullptr;
    cudaGetSymbolAddress((void**)&b0, g_buf0);
    cudaGetSymbolAddress((void**)&b1, g_buf1);

    // one block per physical SM (GB300 = 152, B300 = 148)
    int nsm = 148;
    cudaDeviceGetAttribute(&nsm, cudaDevAttrMultiProcessorCount, 0);

    dim3 grid(nsm), blk(THREADS);

    // input layer: relu(W_in @ x + b_in), scattered via scatter_idx[0]
    gemv_layer<false, false, true><<<grid, blk>>>(
        W_in, nullptr, b_in, x, nullptr, sidx, b0);

    // layer 0: gather g[0], masked GEMV, scatter s[1]
    gemv_layer<true, true, true><<<grid, blk>>>(
        weights, orders, biases, b0, gidx, sidx + DD, b1);

    // layer 1
    gemv_layer<true, true, true><<<grid, blk>>>(
        weights + MATSZ, orders + MATSZ, biases + DD, b1, gidx + DD, sidx + 2 * DD, b0);

    // layer 2
    gemv_layer<true, true, true><<<grid, blk>>>(
        weights + 2 * MATSZ, orders + 2 * MATSZ, biases + 2 * DD, b0, gidx + 2 * DD, sidx + 3 * DD, b1);

    // layer 3: final layer — output is the PRE-scatter activation, straight to d_out
    gemv_layer<true, true, false><<<grid, blk>>>(
        weights + 3 * MATSZ, orders + 3 * MATSZ, biases + 3 * DD, b1, gidx + 3 * DD, nullptr, out);
}